// round 4
// baseline (speedup 1.0000x reference)
#include <cuda_runtime.h>

// RNN_40733469835755 — wavefront RNN, 2 warps per layer (batch-split), 22 warps.
// B=2048, T=512, D=8, H=20, L=10. 128 blocks x 704 threads.
// Warps 2l, 2l+1 own layer l (rows 0-7 / 8-15); warps 20,21 = MLP head for
// timestep u=0/1 + x prefetch. Tick s: layer l does t = 2(s-l), 2(s-l)+1.
// One __syncthreads per tick (266 ticks); intra-tick recurrence is warp-local
// (warp computes all 20 j for its 8 rows) -> __syncwarp only.
// All weights stream from SMEM (broadcast LDS); regs stay low so 22 warps fit
// the 64K regfile (5.5 warps/SMSP for latency hiding).

#define Tn 512
#define Dn 8
#define Hn 20
#define Ln 10
#define BQ 16
#define NT 704
#define NB 128
#define ROWLEN 220
#define UPITCH (BQ * ROWLEN + 16)   // 3536 floats
#define NTICKS (Tn / 2 + Ln)        // 266

typedef unsigned long long u64;

struct __align__(16) Smem {
  float W[Ln][Hn][2 * Hn];   // concat [Wih(pad20) | Whh]
  float bsum[Ln][Hn];
  float fcw[Hn][Hn];
  float fcb[Hn];
  float l2w[Hn];
  float l2b[4];
  float A[2][2][UPITCH];     // [parity][u][row*ROWLEN + slot*20 + k]
};

__device__ __forceinline__ u64 fma2(u64 a, u64 b, u64 c) {
  u64 d;
  asm("fma.rn.f32x2 %0, %1, %2, %3;" : "=l"(d) : "l"(a), "l"(b), "l"(c));
  return d;
}
__device__ __forceinline__ float f2lo(u64 v) { return __uint_as_float((unsigned)v); }
__device__ __forceinline__ float f2hi(u64 v) { return __uint_as_float((unsigned)(v >> 32)); }

__device__ __forceinline__ float ex2a(float x) {
  float r; asm("ex2.approx.f32 %0, %1;" : "=f"(r) : "f"(x)); return r;
}
__device__ __forceinline__ float rcpa(float x) {
  float r; asm("rcp.approx.f32 %0, %1;" : "=f"(r) : "f"(x)); return r;
}
__device__ __forceinline__ float tanh_fast(float x) {
  float z = fminf(fmaxf(x, -9.0f), 9.0f);
  float e = ex2a(z * 2.8853900817779268f);  // 2*log2(e)
  return (e - 1.0f) * rcpa(e + 1.0f);
}

__global__ __launch_bounds__(NT, 1)
void rnn_kernel(const float* __restrict__ x,
                const float* __restrict__ g_wih0,
                const float* __restrict__ g_wih,
                const float* __restrict__ g_whh,
                const float* __restrict__ g_bih,
                const float* __restrict__ g_bhh,
                const float* __restrict__ g_fcw,
                const float* __restrict__ g_fcb,
                const float* __restrict__ g_l2w,
                const float* __restrict__ g_l2b,
                float* __restrict__ y) {
  extern __shared__ float smem_raw[];
  Smem* S = (Smem*)smem_raw;

  const int tid  = threadIdx.x;
  const int wid  = tid >> 5;
  const int lane = tid & 31;
  const int b0   = blockIdx.x * BQ;

  // ---- one-time init ----
  for (int i = tid; i < Ln * Hn * 2 * Hn; i += NT) {
    int k = i % (2 * Hn);
    int j = (i / (2 * Hn)) % Hn;
    int l = i / (2 * Hn * Hn);
    float v;
    if (k < Hn) {
      if (l == 0) v = (k < Dn) ? g_wih0[j * Dn + k] : 0.0f;
      else        v = g_wih[((size_t)(l - 1) * Hn + j) * Hn + k];
    } else {
      v = g_whh[((size_t)l * Hn + j) * Hn + (k - Hn)];
    }
    (&S->W[0][0][0])[i] = v;
  }
  for (int i = tid; i < Ln * Hn; i += NT) (&S->bsum[0][0])[i] = g_bih[i] + g_bhh[i];
  for (int i = tid; i < Hn * Hn; i += NT) (&S->fcw[0][0])[i] = g_fcw[i];
  if (tid < Hn) { S->fcb[tid] = g_fcb[tid]; S->l2w[tid] = g_l2w[tid]; }
  if (tid == 0) S->l2b[0] = g_l2b[0];
  for (int i = tid; i < 2 * 2 * UPITCH; i += NT) (&S->A[0][0][0])[i] = 0.0f;
  __syncthreads();
  // x[t=0] (u0) and x[t=1] (u1) into read-parity (rp=1 at tick 0).
  if (tid < 32) {
    int row = tid >> 1, half = tid & 1;
    float4 v0 = *(const float4*)&x[(((size_t)(b0 + row)) * Tn + 0) * Dn + half * 4];
    float4 v1 = *(const float4*)&x[(((size_t)(b0 + row)) * Tn + 1) * Dn + half * 4];
    *(float4*)&S->A[1][0][row * ROWLEN + half * 4] = v0;
    *(float4*)&S->A[1][1][row * ROWLEN + half * 4] = v1;
  }
  __syncthreads();

  if (wid < 2 * Ln) {
    // ================= layer warp =================
    const int l  = wid >> 1;
    const int bh = wid & 1;               // batch half
    const int jq = lane >> 3;             // 0..3 -> j rows jq*5..+4
    const int bb = (lane & 7) + bh * 8;   // row 0..15
    const int j5 = jq * 5;
    const float* wIn  = &S->W[l][j5][0];   // row stride 40 floats
    const float* wRec = &S->W[l][j5][Hn];
    float bj[5];
#pragma unroll
    for (int jj = 0; jj < 5; ++jj) bj[jj] = S->bsum[l][j5 + jj];
    const int rr = bb * ROWLEN;

    for (int s = 0; s < NTICKS; ++s) {
      const int wp = s & 1, rp = wp ^ 1;
      const int t0 = 2 * (s - l);
      if (t0 >= 0 && t0 < Tn) {
        const float* Ar0 = S->A[rp][0] + rr;
        const float* Ar1 = S->A[rp][1] + rr;
        float* Aw0 = S->A[wp][0] + rr;
        float* Aw1 = S->A[wp][1] + rr;
        u64 a[5], c[5];
#pragma unroll
        for (int jj = 0; jj < 5; ++jj) { a[jj] = 0; c[jj] = 0; }

        // rec tau0: prev tick's tau1 output (warp-local rows)
        {
          const float* pr = Ar1 + (l + 1) * Hn;
#pragma unroll
          for (int kc = 0; kc < 5; ++kc) {
            ulonglong2 v = *(const ulonglong2*)(pr + kc * 4);
#pragma unroll
            for (int jj = 0; jj < 5; ++jj) {
              ulonglong2 w = *(const ulonglong2*)(wRec + jj * 2 * Hn + kc * 4);
              a[jj] = fma2(w.x, v.x, fma2(w.y, v.y, a[jj]));
            }
          }
        }
        // input parts, both timesteps (weights loaded once, reused 2x)
        {
          const float* q0 = Ar0 + l * Hn;
          const float* q1 = Ar1 + l * Hn;
#pragma unroll
          for (int kc = 0; kc < 5; ++kc) {
            ulonglong2 v0 = *(const ulonglong2*)(q0 + kc * 4);
            ulonglong2 v1 = *(const ulonglong2*)(q1 + kc * 4);
#pragma unroll
            for (int jj = 0; jj < 5; ++jj) {
              ulonglong2 w = *(const ulonglong2*)(wIn + jj * 2 * Hn + kc * 4);
              a[jj] = fma2(w.x, v0.x, fma2(w.y, v0.y, a[jj]));
              c[jj] = fma2(w.x, v1.x, fma2(w.y, v1.y, c[jj]));
            }
          }
        }
        // finish tau0, publish (warp-local consumers only)
        {
          float* o0 = Aw0 + (l + 1) * Hn + j5;
#pragma unroll
          for (int jj = 0; jj < 5; ++jj)
            o0[jj] = tanh_fast(f2lo(a[jj]) + f2hi(a[jj]) + bj[jj]);
        }
        __syncwarp();
        // rec tau1: reads tau0 output just written by this warp
        {
          const float* ps = Aw0 + (l + 1) * Hn;
#pragma unroll
          for (int kc = 0; kc < 5; ++kc) {
            ulonglong2 v = *(const ulonglong2*)(ps + kc * 4);
#pragma unroll
            for (int jj = 0; jj < 5; ++jj) {
              ulonglong2 w = *(const ulonglong2*)(wRec + jj * 2 * Hn + kc * 4);
              c[jj] = fma2(w.x, v.x, fma2(w.y, v.y, c[jj]));
            }
          }
          float* o1 = Aw1 + (l + 1) * Hn + j5;
#pragma unroll
          for (int jj = 0; jj < 5; ++jj)
            o1[jj] = tanh_fast(f2lo(c[jj]) + f2hi(c[jj]) + bj[jj]);
        }
      }
      __syncthreads();
    }
  } else {
    // ================= head warps (u = 0/1) =================
    const int u  = wid - 2 * Ln;
    const int jq = lane >> 3;   // fc rows jq*5..+4
    const int b8 = lane & 7;    // rows b8, b8+8
    const int xrow = lane >> 1, xhalf = lane & 1;

    for (int s = 0; s < NTICKS; ++s) {
      const int wp = s & 1, rp = wp ^ 1;
      // prefetch x[t = 2(s+1)+u] into write parity, plane u
      const int tx = 2 * (s + 1) + u;
      if (tx < Tn) {
        float4 v = *(const float4*)&x[(((size_t)(b0 + xrow)) * Tn + tx) * Dn + xhalf * 4];
        *(float4*)&S->A[wp][u][xrow * ROWLEN + xhalf * 4] = v;
      }
      const int t = 2 * (s - Ln) + u;
      if (t >= 2 * (-Ln) + u && s >= Ln) {
        const float* Au = S->A[rp][u];
        // load top-layer h for both rows
        ulonglong2 h0[5], h1[5];
        const float* r0p = Au + b8 * ROWLEN + Ln * Hn;
        const float* r1p = Au + (b8 + 8) * ROWLEN + Ln * Hn;
#pragma unroll
        for (int kc = 0; kc < 5; ++kc) {
          h0[kc] = *(const ulonglong2*)(r0p + kc * 4);
          h1[kc] = *(const ulonglong2*)(r1p + kc * 4);
        }
        float p0 = 0.0f, p1 = 0.0f;
#pragma unroll
        for (int jj = 0; jj < 5; ++jj) {
          int j = jq * 5 + jj;
          const float* wr = &S->fcw[j][0];
          u64 d00 = 0, d01 = 0, d10 = 0, d11 = 0;
#pragma unroll
          for (int kc = 0; kc < 5; ++kc) {
            ulonglong2 w = *(const ulonglong2*)(wr + kc * 4);
            d00 = fma2(w.x, h0[kc].x, d00);
            d01 = fma2(w.y, h0[kc].y, d01);
            d10 = fma2(w.x, h1[kc].x, d10);
            d11 = fma2(w.y, h1[kc].y, d11);
          }
          float fb = S->fcb[j], lw = S->l2w[j];
          float v0 = f2lo(d00) + f2hi(d00) + f2lo(d01) + f2hi(d01) + fb;
          float v1 = f2lo(d10) + f2hi(d10) + f2lo(d11) + f2hi(d11) + fb;
          p0 += fmaxf(v0, 0.0f) * lw;
          p1 += fmaxf(v1, 0.0f) * lw;
        }
        // reduce across jq (lanes differ by bits 3,4)
        p0 += __shfl_xor_sync(0xFFFFFFFFu, p0, 8);
        p0 += __shfl_xor_sync(0xFFFFFFFFu, p0, 16);
        p1 += __shfl_xor_sync(0xFFFFFFFFu, p1, 8);
        p1 += __shfl_xor_sync(0xFFFFFFFFu, p1, 16);
        if (jq == 0) {
          float l2b0 = S->l2b[0];
          y[(size_t)(b0 + b8) * Tn + t]     = p0 + l2b0;
          y[(size_t)(b0 + b8 + 8) * Tn + t] = p1 + l2b0;
        }
      }
      __syncthreads();
    }
  }
}

extern "C" void kernel_launch(void* const* d_in, const int* in_sizes, int n_in,
                              void* d_out, int out_size) {
  (void)in_sizes; (void)n_in; (void)out_size;
  const float* x    = (const float*)d_in[0];
  const float* wih0 = (const float*)d_in[1];
  const float* wih  = (const float*)d_in[2];
  const float* whh  = (const float*)d_in[3];
  const float* bih  = (const float*)d_in[4];
  const float* bhh  = (const float*)d_in[5];
  const float* fcw  = (const float*)d_in[6];
  const float* fcb  = (const float*)d_in[7];
  const float* l2w  = (const float*)d_in[8];
  const float* l2b  = (const float*)d_in[9];
  float* y = (float*)d_out;

  cudaFuncSetAttribute(rnn_kernel, cudaFuncAttributeMaxDynamicSharedMemorySize,
                       (int)sizeof(Smem));
  rnn_kernel<<<NB, NT, sizeof(Smem)>>>(x, wih0, wih, whh, bih, bhh,
                                       fcw, fcb, l2w, l2b, y);
}